// round 2
// baseline (speedup 1.0000x reference)
#include <cuda_runtime.h>
#include <math.h>

#define N_TOK 4096
#define HDIM 512
#define NE 8
#define INTER 1024
#define RSLOT 8192            // N_TOK * topk
#define NSLOT 12288           // RSLOT + N_TOK (shared expert as expert 8)

#define BM 128
#define BN 128
#define BK 8

// ---------------- device scratch (static: no allocations allowed) ----------
__device__ float d_g[(size_t)NSLOT * INTER];   // gate accum -> activated in place
__device__ float d_u[(size_t)NSLOT * INTER];   // up accum
__device__ int   d_counts[9];
__device__ int   d_base[9];
__device__ int   d_cursor[NE];
__device__ int   d_slot_tok[NSLOT];
__device__ float d_slot_w[NSLOT];
__device__ int   d_top_idx[N_TOK * 2];
__device__ float d_top_w[N_TOK * 2];

// ---------------- routing ---------------------------------------------------
__global__ void zero_counts_kernel() {
    if (threadIdx.x < 9) d_counts[threadIdx.x] = 0;
}

// one warp per token: scores = x_row @ router_w, top-2 + renormalized weights
__global__ void router_kernel(const float* __restrict__ x,
                              const float* __restrict__ rw) {
    __shared__ int s_cnt[NE];
    int tid = threadIdx.x;
    if (tid < NE) s_cnt[tid] = 0;
    __syncthreads();

    int warp = tid >> 5, lane = tid & 31;
    int token = blockIdx.x * 8 + warp;

    float acc[NE];
#pragma unroll
    for (int e = 0; e < NE; e++) acc[e] = 0.f;

    const float* xr = x + (size_t)token * HDIM;
#pragma unroll 4
    for (int kk = 0; kk < HDIM / 32; kk++) {
        int k = kk * 32 + lane;
        float xv = xr[k];
        const float4* r4 = (const float4*)(rw + (size_t)k * NE);
        float4 r0 = r4[0], r1 = r4[1];
        acc[0] += xv * r0.x; acc[1] += xv * r0.y;
        acc[2] += xv * r0.z; acc[3] += xv * r0.w;
        acc[4] += xv * r1.x; acc[5] += xv * r1.y;
        acc[6] += xv * r1.z; acc[7] += xv * r1.w;
    }
#pragma unroll
    for (int off = 16; off > 0; off >>= 1)
#pragma unroll
        for (int e = 0; e < NE; e++)
            acc[e] += __shfl_xor_sync(0xffffffffu, acc[e], off);

    if (lane == 0) {
        int i0 = 0;
#pragma unroll
        for (int e = 1; e < NE; e++) if (acc[e] > acc[i0]) i0 = e;
        int i1 = (i0 == 0) ? 1 : 0;
#pragma unroll
        for (int e = 0; e < NE; e++) if (e != i0 && acc[e] > acc[i1]) i1 = e;
        // softmax + top2-renorm collapses to a 2-way logistic
        float p1 = expf(acc[i1] - acc[i0]);           // <= 1
        float inv = 1.f / (1.f + p1);
        d_top_idx[token * 2 + 0] = i0; d_top_w[token * 2 + 0] = inv;
        d_top_idx[token * 2 + 1] = i1; d_top_w[token * 2 + 1] = p1 * inv;
        atomicAdd(&s_cnt[i0], 1);
        atomicAdd(&s_cnt[i1], 1);
    }
    __syncthreads();
    if (tid < NE) atomicAdd(&d_counts[tid], s_cnt[tid]);
}

__global__ void prefix_kernel() {
    int s = 0;
    for (int e = 0; e < NE; e++) {
        d_base[e] = s;
        s += d_counts[e];
        d_cursor[e] = 0;
    }
    d_base[NE] = RSLOT;       // shared expert region
    d_counts[NE] = N_TOK;
}

__global__ void scatter_kernel() {
    int t = blockIdx.x * blockDim.x + threadIdx.x;
    if (t >= N_TOK) return;
#pragma unroll
    for (int j = 0; j < 2; j++) {
        int e = d_top_idx[t * 2 + j];
        int pos = atomicAdd(&d_cursor[e], 1);
        int slot = d_base[e] + pos;
        d_slot_tok[slot] = t;
        d_slot_w[slot]  = d_top_w[t * 2 + j];
    }
    d_slot_tok[RSLOT + t] = t;    // shared expert: every token, weight 1
    d_slot_w[RSLOT + t]  = 1.f;
}

// ---------------- gate/up GEMM: C[slot, INTER] = x[tok] @ W ----------------
// grid: x = INTER/BN (8), y = token tiles (32), z = expert(9) + 9*sel(g/u)
__global__ __launch_bounds__(256, 2) void gemm_gu_kernel(
    const float* __restrict__ x,
    const float* __restrict__ Wg, const float* __restrict__ Wu,
    const float* __restrict__ Sg, const float* __restrict__ Su) {
    int e = blockIdx.z % 9;
    int sel = blockIdx.z / 9;      // 0 = gate, 1 = up
    int cnt = d_counts[e];
    int row0 = blockIdx.y * BM;
    if (row0 >= cnt) return;
    int base = d_base[e];
    const float* B = (e < NE)
        ? ((sel ? Wu : Wg) + (size_t)e * HDIM * INTER)
        : (sel ? Su : Sg);
    float* C = sel ? d_u : d_g;

    __shared__ __align__(16) float AsT[BK][BM];
    __shared__ __align__(16) float Bs[BK][BN];
    __shared__ int s_tok[BM];

    int tid = threadIdx.x;
    if (tid < BM) {
        int gr = row0 + tid;
        s_tok[tid] = (gr < cnt) ? d_slot_tok[base + gr] : -1;
    }
    __syncthreads();

    int tx = tid & 15, ty = tid >> 4;
    int arow = tid >> 1, af4 = (tid & 1) * 4;
    int bk_ = tid >> 5, bc4 = (tid & 31) * 4;
    int n0 = blockIdx.x * BN;
    int atok = s_tok[arow];

    float acc[8][8];
#pragma unroll
    for (int i = 0; i < 8; i++)
#pragma unroll
        for (int j = 0; j < 8; j++) acc[i][j] = 0.f;

    for (int kt = 0; kt < HDIM; kt += BK) {
        float4 av = make_float4(0.f, 0.f, 0.f, 0.f);
        if (atok >= 0)
            av = *(const float4*)(x + (size_t)atok * HDIM + kt + af4);
        float4 bv = *(const float4*)(B + (size_t)(kt + bk_) * INTER + n0 + bc4);
        __syncthreads();
        AsT[af4 + 0][arow] = av.x; AsT[af4 + 1][arow] = av.y;
        AsT[af4 + 2][arow] = av.z; AsT[af4 + 3][arow] = av.w;
        *(float4*)&Bs[bk_][bc4] = bv;
        __syncthreads();
#pragma unroll
        for (int k = 0; k < BK; k++) {
            float a[8], b[8];
            *(float4*)(&a[0]) = *(const float4*)(&AsT[k][ty * 8]);
            *(float4*)(&a[4]) = *(const float4*)(&AsT[k][ty * 8 + 4]);
            *(float4*)(&b[0]) = *(const float4*)(&Bs[k][tx * 8]);
            *(float4*)(&b[4]) = *(const float4*)(&Bs[k][tx * 8 + 4]);
#pragma unroll
            for (int i = 0; i < 8; i++)
#pragma unroll
                for (int j = 0; j < 8; j++)
                    acc[i][j] = fmaf(a[i], b[j], acc[i][j]);
        }
    }

#pragma unroll
    for (int i = 0; i < 8; i++) {
        int r = row0 + ty * 8 + i;
        if (r < cnt) {
            float* cr = C + (size_t)(base + r) * INTER + n0 + tx * 8;
            float4 v0 = make_float4(acc[i][0], acc[i][1], acc[i][2], acc[i][3]);
            float4 v1 = make_float4(acc[i][4], acc[i][5], acc[i][6], acc[i][7]);
            *(float4*)cr = v0;
            *(float4*)(cr + 4) = v1;
        }
    }
}

// ---------------- elementwise SiLU(g) * u -> d_g ---------------------------
__global__ void act_kernel() {
    size_t i = (size_t)blockIdx.x * blockDim.x + threadIdx.x;
    float4 g = ((float4*)d_g)[i];
    float4 u = ((float4*)d_u)[i];
    g.x = g.x / (1.f + __expf(-g.x)) * u.x;
    g.y = g.y / (1.f + __expf(-g.y)) * u.y;
    g.z = g.z / (1.f + __expf(-g.z)) * u.z;
    g.w = g.w / (1.f + __expf(-g.w)) * u.w;
    ((float4*)d_g)[i] = g;
}

// ---------------- down GEMM: out[tok] += w * act[slot] @ Wd ----------------
// grid: x = HDIM/BN (4), y = token tiles (32), z = expert (9)
__global__ __launch_bounds__(256, 2) void gemm_down_kernel(
    const float* __restrict__ Wd, const float* __restrict__ Sd,
    float* __restrict__ out) {
    int e = blockIdx.z;
    int cnt = d_counts[e];
    int row0 = blockIdx.y * BM;
    if (row0 >= cnt) return;
    int base = d_base[e];
    const float* B = (e < NE) ? (Wd + (size_t)e * INTER * HDIM) : Sd;

    __shared__ __align__(16) float AsT[BK][BM];
    __shared__ __align__(16) float Bs[BK][BN];
    __shared__ int s_tok[BM];
    __shared__ float s_w[BM];

    int tid = threadIdx.x;
    if (tid < BM) {
        int gr = row0 + tid;
        s_tok[tid] = (gr < cnt) ? d_slot_tok[base + gr] : 0;
        s_w[tid]   = (gr < cnt) ? d_slot_w[base + gr] : 0.f;
    }
    __syncthreads();

    int tx = tid & 15, ty = tid >> 4;
    int arow = tid >> 1, af4 = (tid & 1) * 4;
    int bk_ = tid >> 5, bc4 = (tid & 31) * 4;
    int n0 = blockIdx.x * BN;
    const float* Arow = d_g + (size_t)(base + row0 + arow) * INTER;  // stays < NSLOT

    float acc[8][8];
#pragma unroll
    for (int i = 0; i < 8; i++)
#pragma unroll
        for (int j = 0; j < 8; j++) acc[i][j] = 0.f;

    for (int kt = 0; kt < INTER; kt += BK) {
        float4 av = *(const float4*)(Arow + kt + af4);
        float4 bv = *(const float4*)(B + (size_t)(kt + bk_) * HDIM + n0 + bc4);
        __syncthreads();
        AsT[af4 + 0][arow] = av.x; AsT[af4 + 1][arow] = av.y;
        AsT[af4 + 2][arow] = av.z; AsT[af4 + 3][arow] = av.w;
        *(float4*)&Bs[bk_][bc4] = bv;
        __syncthreads();
#pragma unroll
        for (int k = 0; k < BK; k++) {
            float a[8], b[8];
            *(float4*)(&a[0]) = *(const float4*)(&AsT[k][ty * 8]);
            *(float4*)(&a[4]) = *(const float4*)(&AsT[k][ty * 8 + 4]);
            *(float4*)(&b[0]) = *(const float4*)(&Bs[k][tx * 8]);
            *(float4*)(&b[4]) = *(const float4*)(&Bs[k][tx * 8 + 4]);
#pragma unroll
            for (int i = 0; i < 8; i++)
#pragma unroll
                for (int j = 0; j < 8; j++)
                    acc[i][j] = fmaf(a[i], b[j], acc[i][j]);
        }
    }

#pragma unroll
    for (int i = 0; i < 8; i++) {
        int r = row0 + ty * 8 + i;
        if (r < cnt) {
            int tok = s_tok[ty * 8 + i];
            float w = s_w[ty * 8 + i];
            float* orow = out + (size_t)tok * HDIM + n0 + tx * 8;
#pragma unroll
            for (int j = 0; j < 8; j++)
                atomicAdd(orow + j, w * acc[i][j]);
        }
    }
}

// ---------------- launch ----------------------------------------------------
extern "C" void kernel_launch(void* const* d_in, const int* in_sizes, int n_in,
                              void* d_out, int out_size) {
    const float* x  = (const float*)d_in[0];
    const float* rw = (const float*)d_in[1];
    const float* Wg = (const float*)d_in[2];
    const float* Wu = (const float*)d_in[3];
    const float* Wd = (const float*)d_in[4];
    const float* Sg = (const float*)d_in[5];
    const float* Su = (const float*)d_in[6];
    const float* Sd = (const float*)d_in[7];
    float* out = (float*)d_out;

    cudaMemsetAsync(d_out, 0, (size_t)out_size * sizeof(float));
    zero_counts_kernel<<<1, 32>>>();
    router_kernel<<<N_TOK / 8, 256>>>(x, rw);
    prefix_kernel<<<1, 1>>>();
    scatter_kernel<<<(N_TOK + 255) / 256, 256>>>();

    dim3 ggu(INTER / BN, (N_TOK + BM - 1) / BM, 18);   // 9 experts x {gate,up}
    gemm_gu_kernel<<<ggu, 256>>>(x, Wg, Wu, Sg, Su);

    act_kernel<<<((size_t)NSLOT * INTER / 4) / 256, 256>>>();

    dim3 gdn(HDIM / BN, (N_TOK + BM - 1) / BM, 9);
    gemm_down_kernel<<<gdn, 256>>>(Wd, Sd, out);
}

// round 8
// speedup vs baseline: 1.9376x; 1.9376x over previous
#include <cuda_runtime.h>
#include <cuda_bf16.h>
#include <math.h>
#include <stdint.h>

#define N_TOK 4096
#define HDIM 512
#define NE 8
#define INTER 1024
#define RSLOT 8192            // N_TOK * topk
#define NSLOT 12288           // RSLOT + N_TOK (shared expert appended)

#define KC 32                 // K-chunk staged in smem
#define APAD 40               // smem row stride in bf16 (80B: 16B-aligned, conflict-light)

// ---------------- device scratch (static: no allocations allowed) ----------
__device__ float d_g[(size_t)NSLOT * INTER];
__device__ float d_u[(size_t)NSLOT * INTER];
__device__ __nv_bfloat16 d_wg_hi[(size_t)9 * INTER * HDIM];       // [e][i][h] K-major
__device__ __nv_bfloat16 d_wg_lo[(size_t)9 * INTER * HDIM];
__device__ __nv_bfloat16 d_wu_hi[(size_t)9 * INTER * HDIM];
__device__ __nv_bfloat16 d_wu_lo[(size_t)9 * INTER * HDIM];
__device__ __nv_bfloat16 d_wd_hi[(size_t)9 * HDIM * INTER];       // [e][h][i] K-major
__device__ __nv_bfloat16 d_wd_lo[(size_t)9 * HDIM * INTER];
__device__ int   d_counts[9];
__device__ int   d_base[9];
__device__ int   d_cursor[NE];
__device__ int   d_slot_tok[NSLOT];
__device__ float d_slot_w[NSLOT];
__device__ int   d_top_idx[N_TOK * 2];
__device__ float d_top_w[N_TOK * 2];

// ---------------- mma.sync helper (base ISA, compiles for compute_103) ------
__device__ __forceinline__ void mma16816(float* c, const uint32_t* a,
                                         const uint32_t* b) {
    asm volatile(
        "mma.sync.aligned.m16n8k16.row.col.f32.bf16.bf16.f32 "
        "{%0,%1,%2,%3}, {%4,%5,%6,%7}, {%8,%9}, {%0,%1,%2,%3};"
        : "+f"(c[0]), "+f"(c[1]), "+f"(c[2]), "+f"(c[3])
        : "r"(a[0]), "r"(a[1]), "r"(a[2]), "r"(a[3]), "r"(b[0]), "r"(b[1]));
}

// ---------------- routing (unchanged, proven) -------------------------------
__global__ void zero_counts_kernel() {
    if (threadIdx.x < 9) d_counts[threadIdx.x] = 0;
}

__global__ void router_kernel(const float* __restrict__ x,
                              const float* __restrict__ rw) {
    __shared__ int s_cnt[NE];
    int tid = threadIdx.x;
    if (tid < NE) s_cnt[tid] = 0;
    __syncthreads();

    int warp = tid >> 5, lane = tid & 31;
    int token = blockIdx.x * 8 + warp;

    float acc[NE];
#pragma unroll
    for (int e = 0; e < NE; e++) acc[e] = 0.f;

    const float* xr = x + (size_t)token * HDIM;
#pragma unroll 4
    for (int kk = 0; kk < HDIM / 32; kk++) {
        int k = kk * 32 + lane;
        float xv = xr[k];
        const float4* r4 = (const float4*)(rw + (size_t)k * NE);
        float4 r0 = r4[0], r1 = r4[1];
        acc[0] += xv * r0.x; acc[1] += xv * r0.y;
        acc[2] += xv * r0.z; acc[3] += xv * r0.w;
        acc[4] += xv * r1.x; acc[5] += xv * r1.y;
        acc[6] += xv * r1.z; acc[7] += xv * r1.w;
    }
#pragma unroll
    for (int off = 16; off > 0; off >>= 1)
#pragma unroll
        for (int e = 0; e < NE; e++)
            acc[e] += __shfl_xor_sync(0xffffffffu, acc[e], off);

    if (lane == 0) {
        int i0 = 0;
#pragma unroll
        for (int e = 1; e < NE; e++) if (acc[e] > acc[i0]) i0 = e;
        int i1 = (i0 == 0) ? 1 : 0;
#pragma unroll
        for (int e = 0; e < NE; e++) if (e != i0 && acc[e] > acc[i1]) i1 = e;
        float p1 = expf(acc[i1] - acc[i0]);
        float inv = 1.f / (1.f + p1);
        d_top_idx[token * 2 + 0] = i0; d_top_w[token * 2 + 0] = inv;
        d_top_idx[token * 2 + 1] = i1; d_top_w[token * 2 + 1] = p1 * inv;
        atomicAdd(&s_cnt[i0], 1);
        atomicAdd(&s_cnt[i1], 1);
    }
    __syncthreads();
    if (tid < NE) atomicAdd(&d_counts[tid], s_cnt[tid]);
}

__global__ void prefix_kernel() {
    int s = 0;
    for (int e = 0; e < NE; e++) {
        d_base[e] = s;
        s += d_counts[e];
        d_cursor[e] = 0;
    }
    d_base[NE] = RSLOT;
    d_counts[NE] = N_TOK;
}

__global__ void scatter_kernel() {
    int t = blockIdx.x * blockDim.x + threadIdx.x;
    if (t >= N_TOK) return;
#pragma unroll
    for (int j = 0; j < 2; j++) {
        int e = d_top_idx[t * 2 + j];
        int pos = atomicAdd(&d_cursor[e], 1);
        int slot = d_base[e] + pos;
        d_slot_tok[slot] = t;
        d_slot_w[slot]  = d_top_w[t * 2 + j];
    }
    d_slot_tok[RSLOT + t] = t;
    d_slot_w[RSLOT + t]  = 1.f;
}

// ---------------- weight convert: fp32 -> transposed K-major bf16 hi/lo ----
__global__ void conv_w_kernel(const float* __restrict__ Wg,
                              const float* __restrict__ Wu,
                              const float* __restrict__ Wd,
                              const float* __restrict__ Sg,
                              const float* __restrict__ Su,
                              const float* __restrict__ Sd) {
    int z = blockIdx.z;
    int grp = z / 9;
    int e = z % 9;
    int R = (grp == 2) ? INTER : HDIM;
    int C = (grp == 2) ? HDIM : INTER;
    if (blockIdx.x * 32 >= (unsigned)C || blockIdx.y * 32 >= (unsigned)R) return;

    const float* src;
    __nv_bfloat16 *dh, *dl;
    if (grp == 0) {
        src = (e < NE) ? Wg + (size_t)e * HDIM * INTER : Sg;
        dh = d_wg_hi + (size_t)e * INTER * HDIM;
        dl = d_wg_lo + (size_t)e * INTER * HDIM;
    } else if (grp == 1) {
        src = (e < NE) ? Wu + (size_t)e * HDIM * INTER : Su;
        dh = d_wu_hi + (size_t)e * INTER * HDIM;
        dl = d_wu_lo + (size_t)e * INTER * HDIM;
    } else {
        src = (e < NE) ? Wd + (size_t)e * INTER * HDIM : Sd;
        dh = d_wd_hi + (size_t)e * HDIM * INTER;
        dl = d_wd_lo + (size_t)e * HDIM * INTER;
    }

    __shared__ float tile[32][33];
    int tx = threadIdx.x, ty = threadIdx.y;
    int c0 = blockIdx.x * 32, r0 = blockIdx.y * 32;
#pragma unroll
    for (int k = 0; k < 4; k++)
        tile[ty + k * 8][tx] = src[(size_t)(r0 + ty + k * 8) * C + c0 + tx];
    __syncthreads();
#pragma unroll
    for (int k = 0; k < 4; k++) {
        float v = tile[tx][ty + k * 8];
        size_t o = (size_t)(c0 + ty + k * 8) * R + r0 + tx;
        __nv_bfloat16 h = __float2bfloat16(v);
        dh[o] = h;
        dl[o] = __float2bfloat16(v - __bfloat162float(h));
    }
}

// ---------------- gate/up mma GEMM ------------------------------------------
// grid: x = INTER/128 (8), y = 32 slot tiles, z = expert(9) + 9*sel
__global__ __launch_bounds__(256) void gemm_gu_mma(const float* __restrict__ x) {
    __shared__ int s_tok[128];
    __shared__ __align__(16) __nv_bfloat16 Ah[128][APAD], Al[128][APAD];
    __shared__ __align__(16) __nv_bfloat16 Bh[128][APAD], Bl[128][APAD];

    int z = blockIdx.z;
    int e = z % 9, sel = z / 9;
    int cnt = d_counts[e];
    int row0 = blockIdx.y * 128;
    if (row0 >= cnt) return;
    int base = d_base[e];
    int n0 = blockIdx.x * 128;
    int t = threadIdx.x;
    int wid = t >> 5, lane = t & 31;
    int g = lane >> 2, tg = lane & 3;
    int mrow0 = (wid >> 2) * 64, ncol0 = (wid & 3) * 32;

    if (t < 128) {
        int gr = row0 + t;
        s_tok[t] = (gr < cnt) ? d_slot_tok[base + gr] : -1;
    }
    __syncthreads();

    const __nv_bfloat16* wh = (sel ? d_wu_hi : d_wg_hi) + (size_t)e * INTER * HDIM;
    const __nv_bfloat16* wl = (sel ? d_wu_lo : d_wg_lo) + (size_t)e * INTER * HDIM;
    float* C = sel ? d_u : d_g;

    int arow = t >> 1, acol0 = (t & 1) * 16;
    int tokA = s_tok[arow];
    const float* rowptr = (tokA >= 0) ? x + (size_t)tokA * HDIM : (const float*)0;

    float acc[4][4][4];
#pragma unroll
    for (int i = 0; i < 4; i++)
#pragma unroll
        for (int j = 0; j < 4; j++)
#pragma unroll
            for (int k = 0; k < 4; k++) acc[i][j][k] = 0.f;

    for (int kt = 0; kt < HDIM; kt += KC) {
        // stage A: fp32 -> bf16 hi/lo
#pragma unroll
        for (int j = 0; j < 4; j++) {
            int c = acol0 + j * 4;
            float4 v = rowptr ? *(const float4*)(rowptr + kt + c)
                              : make_float4(0.f, 0.f, 0.f, 0.f);
            __nv_bfloat162 h01 = __floats2bfloat162_rn(v.x, v.y);
            __nv_bfloat162 h23 = __floats2bfloat162_rn(v.z, v.w);
            __nv_bfloat162 l01 = __floats2bfloat162_rn(
                v.x - __bfloat162float(h01.x), v.y - __bfloat162float(h01.y));
            __nv_bfloat162 l23 = __floats2bfloat162_rn(
                v.z - __bfloat162float(h23.x), v.w - __bfloat162float(h23.y));
            *(uint2*)&Ah[arow][c] = make_uint2(*(uint32_t*)&h01, *(uint32_t*)&h23);
            *(uint2*)&Al[arow][c] = make_uint2(*(uint32_t*)&l01, *(uint32_t*)&l23);
        }
        // stage B: bf16 straight copy
#pragma unroll
        for (int q = 0; q < 2; q++) {
            int v = t * 2 + q;
            int rb = v >> 2, seg = v & 3;
            size_t go = (size_t)(n0 + rb) * HDIM + kt + seg * 8;
            *(uint4*)&Bh[rb][seg * 8] = *(const uint4*)(wh + go);
            *(uint4*)&Bl[rb][seg * 8] = *(const uint4*)(wl + go);
        }
        __syncthreads();

#pragma unroll
        for (int ks = 0; ks < 2; ks++) {
            int kb = ks * 16;
            uint32_t afh[4][4], afl[4][4], bfh[4][2], bfl[4][2];
#pragma unroll
            for (int i = 0; i < 4; i++) {
                int r = mrow0 + i * 16 + g;
                afh[i][0] = *(const uint32_t*)&Ah[r][kb + 2 * tg];
                afh[i][1] = *(const uint32_t*)&Ah[r + 8][kb + 2 * tg];
                afh[i][2] = *(const uint32_t*)&Ah[r][kb + 2 * tg + 8];
                afh[i][3] = *(const uint32_t*)&Ah[r + 8][kb + 2 * tg + 8];
                afl[i][0] = *(const uint32_t*)&Al[r][kb + 2 * tg];
                afl[i][1] = *(const uint32_t*)&Al[r + 8][kb + 2 * tg];
                afl[i][2] = *(const uint32_t*)&Al[r][kb + 2 * tg + 8];
                afl[i][3] = *(const uint32_t*)&Al[r + 8][kb + 2 * tg + 8];
            }
#pragma unroll
            for (int j = 0; j < 4; j++) {
                int r = ncol0 + j * 8 + g;
                bfh[j][0] = *(const uint32_t*)&Bh[r][kb + 2 * tg];
                bfh[j][1] = *(const uint32_t*)&Bh[r][kb + 2 * tg + 8];
                bfl[j][0] = *(const uint32_t*)&Bl[r][kb + 2 * tg];
                bfl[j][1] = *(const uint32_t*)&Bl[r][kb + 2 * tg + 8];
            }
#pragma unroll
            for (int i = 0; i < 4; i++)
#pragma unroll
                for (int j = 0; j < 4; j++) {
                    mma16816(acc[i][j], afh[i], bfh[j]);
                    mma16816(acc[i][j], afh[i], bfl[j]);
                    mma16816(acc[i][j], afl[i], bfh[j]);
                }
        }
        __syncthreads();
    }

    // epilogue: write fp32 tiles
#pragma unroll
    for (int i = 0; i < 4; i++) {
        int lr = mrow0 + i * 16 + g;
#pragma unroll
        for (int j = 0; j < 4; j++) {
            int col = n0 + ncol0 + j * 8 + 2 * tg;
            int gr0 = row0 + lr;
            if (gr0 < cnt) {
                float* cr = C + (size_t)(base + gr0) * INTER + col;
                cr[0] = acc[i][j][0]; cr[1] = acc[i][j][1];
            }
            int gr1 = gr0 + 8;
            if (gr1 < cnt) {
                float* cr = C + (size_t)(base + gr1) * INTER + col;
                cr[0] = acc[i][j][2]; cr[1] = acc[i][j][3];
            }
        }
    }
}

// ---------------- elementwise SiLU(g) * u -> d_g ---------------------------
__global__ void act_kernel() {
    size_t i = (size_t)blockIdx.x * blockDim.x + threadIdx.x;
    float4 g = ((float4*)d_g)[i];
    float4 u = ((float4*)d_u)[i];
    g.x = g.x / (1.f + __expf(-g.x)) * u.x;
    g.y = g.y / (1.f + __expf(-g.y)) * u.y;
    g.z = g.z / (1.f + __expf(-g.z)) * u.z;
    g.w = g.w / (1.f + __expf(-g.w)) * u.w;
    ((float4*)d_g)[i] = g;
}

// ---------------- down mma GEMM + weighted atomic epilogue ------------------
// grid: x = HDIM/128 (4), y = 32 slot tiles, z = expert 0..8
__global__ __launch_bounds__(256) void gemm_dn_mma(float* __restrict__ out) {
    __shared__ int s_tok[128];
    __shared__ float s_w[128];
    __shared__ __align__(16) __nv_bfloat16 Ah[128][APAD], Al[128][APAD];
    __shared__ __align__(16) __nv_bfloat16 Bh[128][APAD], Bl[128][APAD];

    int e = blockIdx.z;
    int cnt = d_counts[e];
    int row0 = blockIdx.y * 128;
    if (row0 >= cnt) return;
    int base = d_base[e];
    int n0 = blockIdx.x * 128;
    int t = threadIdx.x;
    int wid = t >> 5, lane = t & 31;
    int g = lane >> 2, tg = lane & 3;
    int mrow0 = (wid >> 2) * 64, ncol0 = (wid & 3) * 32;

    if (t < 128) {
        int gr = row0 + t;
        s_tok[t] = (gr < cnt) ? d_slot_tok[base + gr] : 0;
        s_w[t]   = (gr < cnt) ? d_slot_w[base + gr] : 0.f;
    }
    __syncthreads();

    const __nv_bfloat16* wh = d_wd_hi + (size_t)e * HDIM * INTER;
    const __nv_bfloat16* wl = d_wd_lo + (size_t)e * HDIM * INTER;

    int arow = t >> 1, acol0 = (t & 1) * 16;
    const float* rowptr = d_g + (size_t)(base + row0 + arow) * INTER;

    float acc[4][4][4];
#pragma unroll
    for (int i = 0; i < 4; i++)
#pragma unroll
        for (int j = 0; j < 4; j++)
#pragma unroll
            for (int k = 0; k < 4; k++) acc[i][j][k] = 0.f;

    for (int kt = 0; kt < INTER; kt += KC) {
#pragma unroll
        for (int j = 0; j < 4; j++) {
            int c = acol0 + j * 4;
            float4 v = *(const float4*)(rowptr + kt + c);
            __nv_bfloat162 h01 = __floats2bfloat162_rn(v.x, v.y);
            __nv_bfloat162 h23 = __floats2bfloat162_rn(v.z, v.w);
            __nv_bfloat162 l01 = __floats2bfloat162_rn(
                v.x - __bfloat162float(h01.x), v.y - __bfloat162float(h01.y));
            __nv_bfloat162 l23 = __floats2bfloat162_rn(
                v.z - __bfloat162float(h23.x), v.w - __bfloat162float(h23.y));
            *(uint2*)&Ah[arow][c] = make_uint2(*(uint32_t*)&h01, *(uint32_t*)&h23);
            *(uint2*)&Al[arow][c] = make_uint2(*(uint32_t*)&l01, *(uint32_t*)&l23);
        }
#pragma unroll
        for (int q = 0; q < 2; q++) {
            int v = t * 2 + q;
            int rb = v >> 2, seg = v & 3;
            size_t go = (size_t)(n0 + rb) * INTER + kt + seg * 8;
            *(uint4*)&Bh[rb][seg * 8] = *(const uint4*)(wh + go);
            *(uint4*)&Bl[rb][seg * 8] = *(const uint4*)(wl + go);
        }
        __syncthreads();

#pragma unroll
        for (int ks = 0; ks < 2; ks++) {
            int kb = ks * 16;
            uint32_t afh[4][4], afl[4][4], bfh[4][2], bfl[4][2];
#pragma unroll
            for (int i = 0; i < 4; i++) {
                int r = mrow0 + i * 16 + g;
                afh[i][0] = *(const uint32_t*)&Ah[r][kb + 2 * tg];
                afh[i][1] = *(const uint32_t*)&Ah[r + 8][kb + 2 * tg];
                afh[i][2] = *(const uint32_t*)&Ah[r][kb + 2 * tg + 8];
                afh[i][3] = *(const uint32_t*)&Ah[r + 8][kb + 2 * tg + 8];
                afl[i][0] = *(const uint32_t*)&Al[r][kb + 2 * tg];
                afl[i][1] = *(const uint32_t*)&Al[r + 8][kb + 2 * tg];
                afl[i][2] = *(const uint32_t*)&Al[r][kb + 2 * tg + 8];
                afl[i][3] = *(const uint32_t*)&Al[r + 8][kb + 2 * tg + 8];
            }
#pragma unroll
            for (int j = 0; j < 4; j++) {
                int r = ncol0 + j * 8 + g;
                bfh[j][0] = *(const uint32_t*)&Bh[r][kb + 2 * tg];
                bfh[j][1] = *(const uint32_t*)&Bh[r][kb + 2 * tg + 8];
                bfl[j][0] = *(const uint32_t*)&Bl[r][kb + 2 * tg];
                bfl[j][1] = *(const uint32_t*)&Bl[r][kb + 2 * tg + 8];
            }
#pragma unroll
            for (int i = 0; i < 4; i++)
#pragma unroll
                for (int j = 0; j < 4; j++) {
                    mma16816(acc[i][j], afh[i], bfh[j]);
                    mma16816(acc[i][j], afh[i], bfl[j]);
                    mma16816(acc[i][j], afl[i], bfh[j]);
                }
        }
        __syncthreads();
    }

    // epilogue: out[tok] += w * D  (atomic, 2 rows per tile)
#pragma unroll
    for (int i = 0; i < 4; i++) {
        int lr = mrow0 + i * 16 + g;
#pragma unroll
        for (int j = 0; j < 4; j++) {
            int col = n0 + ncol0 + j * 8 + 2 * tg;
            int gr0 = row0 + lr;
            if (gr0 < cnt) {
                int tok = s_tok[lr];
                float w = s_w[lr];
                float* dst = out + (size_t)tok * HDIM + col;
                atomicAdd(dst + 0, w * acc[i][j][0]);
                atomicAdd(dst + 1, w * acc[i][j][1]);
            }
            int gr1 = gr0 + 8;
            if (gr1 < cnt) {
                int tok = s_tok[lr + 8];
                float w = s_w[lr + 8];
                float* dst = out + (size_t)tok * HDIM + col;
                atomicAdd(dst + 0, w * acc[i][j][2]);
                atomicAdd(dst + 1, w * acc[i][j][3]);
            }
        }
    }
}

// ---------------- launch ----------------------------------------------------
extern "C" void kernel_launch(void* const* d_in, const int* in_sizes, int n_in,
                              void* d_out, int out_size) {
    const float* x  = (const float*)d_in[0];
    const float* rw = (const float*)d_in[1];
    const float* Wg = (const float*)d_in[2];
    const float* Wu = (const float*)d_in[3];
    const float* Wd = (const float*)d_in[4];
    const float* Sg = (const float*)d_in[5];
    const float* Su = (const float*)d_in[6];
    const float* Sd = (const float*)d_in[7];
    float* out = (float*)d_out;

    cudaMemsetAsync(d_out, 0, (size_t)out_size * sizeof(float));
    zero_counts_kernel<<<1, 32>>>();
    router_kernel<<<N_TOK / 8, 256>>>(x, rw);
    prefix_kernel<<<1, 1>>>();
    scatter_kernel<<<(N_TOK + 255) / 256, 256>>>();

    conv_w_kernel<<<dim3(32, 32, 27), dim3(32, 8)>>>(Wg, Wu, Wd, Sg, Su, Sd);

    gemm_gu_mma<<<dim3(INTER / 128, 32, 18), 256>>>(x);

    act_kernel<<<((size_t)NSLOT * INTER / 4) / 256, 256>>>();

    gemm_dn_mma<<<dim3(HDIM / 128, 32, 9), 256>>>(out);
}